// round 2
// baseline (speedup 1.0000x reference)
#include <cuda_runtime.h>
#include <stdint.h>
#include <math.h>

#define BB  256
#define INN 512
#define OUT 1024

// ---------------- global scratch (no allocations allowed) ----------------
__device__ __align__(16) uint8_t g_xb[BB * INN];          // raw fp8 bytes of x
__device__ __align__(16) uint8_t g_wb[OUT * INN];         // PERMUTED fp8 bytes of w
__device__ __align__(16) uint8_t g_lut[2 * 65536];        // [0:64K) mul, [64K:128K) add

// ---------------- byte permutation: (s e3 e2 e1 e0 m2 m1 m0) -> (s m2 m1 m0 e1 e0 e3 e2)
// puts mantissa + low-exponent bits into shared-mem bank bits addr[6:2]
__device__ __forceinline__ int perm8(int b) {
    int s = b & 0x80;
    int e = (b >> 3) & 15;
    int m = b & 7;
    return s | (m << 4) | ((e & 3) << 2) | (e >> 2);
}
__device__ __forceinline__ int unperm8(int p) {
    int s = p & 0x80;
    int m = (p >> 4) & 7;
    int e = ((p & 3) << 2) | ((p >> 2) & 3);
    return s | (e << 3) | m;
}

// ---------------- exact E4M3 helpers (match JAX reference bit-for-bit) ----------------
__device__ __forceinline__ float dec8(int b) {
    int e = (b >> 3) & 15;
    int m = b & 7;
    float mag = e ? ldexpf((float)(8 + m), e - 10)   // (1+m/8)*2^(e-7)
                  : ldexpf((float)m, -9);            // subnormal: (m/8)*2^-6
    return (b & 0x80) ? -mag : mag;                  // note: 0x80 -> -0.0f
}

// quant_e4m3 from the reference: RNE on grid 2^(e-3), e = max(floor(log2|a|), -6),
// saturate at 448, sign via (v < 0 ? -q : q)  (strict <, so -0 input -> +0)
__device__ __forceinline__ float quantf(float v) {
    float a = fabsf(v);
    if (a == 0.0f) return 0.0f;
    int ex;
    float f = frexpf(a, &ex); (void)f;     // a = f*2^ex, f in [0.5,1): floor(log2 a) = ex-1
    int e = ex - 1;
    if (e < -6) e = -6;
    float step = ldexpf(1.0f, e - 3);
    float q = rintf(a / step) * step;       // rintf = round-half-even; a/step exact (pow2)
    q = fminf(q, 448.0f);
    return (v < 0.0f) ? -q : q;             // can produce -0.0 (matches reference)
}

__device__ __forceinline__ int enc8(float q) {
    int s = signbit(q) ? 0x80 : 0;
    float a = fabsf(q);
    if (a == 0.0f) return s;                // preserves -0.0 as 0x80
    int ex;
    float f = frexpf(a, &ex); (void)f;
    int e = ex - 1;
    int ef, m;
    if (e < -6) { ef = 0;     m = (int)ldexpf(a, 9); }          // a = m*2^-9 exactly
    else        { ef = e + 7; m = (int)ldexpf(a, 3 - e) - 8; }  // a = (8+m)*2^(e-3)
    return s | (ef << 3) | m;
}

// ---------------- kernel 1: spike bits -> fp8 bytes ----------------
__global__ void encode_kernel(const float* __restrict__ x, const float* __restrict__ w) {
    int tid = blockIdx.x * blockDim.x + threadIdx.x;
    const int NX = BB * INN;
    const int NT = NX + OUT * INN;
    if (tid >= NT) return;
    const float* src = (tid < NX) ? (x + (size_t)tid * 8)
                                  : (w + (size_t)(tid - NX) * 8);
    float4 a = *(const float4*)(src);
    float4 b = *(const float4*)(src + 4);
    int byte = ((a.x != 0.0f) ? 128 : 0) | ((a.y != 0.0f) ? 64 : 0)
             | ((a.z != 0.0f) ? 32 : 0)  | ((a.w != 0.0f) ? 16 : 0)
             | ((b.x != 0.0f) ? 8 : 0)   | ((b.y != 0.0f) ? 4 : 0)
             | ((b.z != 0.0f) ? 2 : 0)   | ((b.w != 0.0f) ? 1 : 0);
    if (tid < NX) g_xb[tid] = (uint8_t)byte;
    else          g_wb[tid - NX] = (uint8_t)perm8(byte);
}

// ---------------- kernel 2: build both 64KB LUTs ----------------
__global__ void lut_kernel() {
    int i = blockIdx.x * 256 + threadIdx.x;   // 0..65535
    int hi = i >> 8, lo = i & 255;
    // mul LUT: index = x_raw*256 + w_perm  -> raw p byte
    {
        float xv = dec8(hi);
        float wv = dec8(unperm8(lo));
        g_lut[i] = (uint8_t)enc8(quantf(xv * wv));
    }
    // add LUT: index = p_raw*256 + acc_perm -> perm(new acc byte)
    {
        float pv = dec8(hi);
        float av = dec8(unperm8(lo));
        g_lut[65536 + i] = (uint8_t)perm8(enc8(quantf(av + pv)));
    }
}

// ---------------- kernel 3: main chain ----------------
#define BT 16
#define OT 128
#define WSTRIDE 516                      // 129 words: odd -> conflict-free per-lane rows
#define SM_X   131072
#define SM_W   (SM_X + BT * INN)         // 139264
#define SM_TOTAL (SM_W + OT * WSTRIDE)   // 205312 bytes

__global__ __launch_bounds__(1024, 1)
void main_kernel(float* __restrict__ out) {
    extern __shared__ uint8_t sm[];
    int t = threadIdx.x;
    int otile = (blockIdx.x & 7) * OT;
    int btile = (blockIdx.x >> 3) * BT;

    // copy 128KB of LUTs (uint4, fully coalesced/conflict-free)
    {
        const uint4* src = (const uint4*)g_lut;
        uint4* dst = (uint4*)sm;
        #pragma unroll
        for (int k = 0; k < 8; k++) dst[t + k * 1024] = src[t + k * 1024];
    }
    // x tile: 16 rows x 512 bytes, contiguous
    if (t < 512)
        ((uint4*)(sm + SM_X))[t] = ((const uint4*)(g_xb + (size_t)btile * INN))[t];
    // w tile: 128 rows x 512 bytes into stride-516 rows (u32 stores; ~4-way, one-time)
    {
        int row = t >> 3, part = t & 7;
        const uint4* src = (const uint4*)(g_wb + (size_t)(otile + row) * INN + part * 64);
        uint32_t* dst = (uint32_t*)(sm + SM_W + row * WSTRIDE + part * 64);
        #pragma unroll
        for (int j = 0; j < 4; j++) {
            uint4 v = src[j];
            dst[j * 4 + 0] = v.x; dst[j * 4 + 1] = v.y;
            dst[j * 4 + 2] = v.z; dst[j * 4 + 3] = v.w;
        }
    }
    __syncthreads();

    int o  = t & 127;
    int bA = t >> 7;       // 0..7
    int bB = bA + 8;
    const uint8_t*  mul  = sm;
    const uint8_t*  addt = sm + 65536;
    const uint32_t* xsA  = (const uint32_t*)(sm + SM_X + bA * INN);
    const uint32_t* xsB  = (const uint32_t*)(sm + SM_X + bB * INN);
    const uint32_t* ws   = (const uint32_t*)(sm + SM_W + o * WSTRIDE);

    unsigned accA = 0, accB = 0;   // perm(+0) == 0; exact (see analysis)
    #pragma unroll 4
    for (int iw = 0; iw < 128; iw++) {
        unsigned w4  = ws[iw];
        unsigned xA4 = xsA[iw];    // warp-uniform -> broadcast
        unsigned xB4 = xsB[iw];
        #pragma unroll
        for (int j = 0; j < 4; j++) {
            unsigned wv = (w4  >> (8 * j)) & 255u;
            unsigned xA = (xA4 >> (8 * j)) & 255u;
            unsigned xB = (xB4 >> (8 * j)) & 255u;
            unsigned pA = mul[(xA << 8) | wv];
            unsigned pB = mul[(xB << 8) | wv];
            accA = addt[(pA << 8) | accA];
            accB = addt[(pB << 8) | accB];
        }
    }

    int rawA = unperm8((int)accA); if ((rawA & 0x7f) == 0) rawA = 0;  // -0 -> all-zero bits
    int rawB = unperm8((int)accB); if ((rawB & 0x7f) == 0) rawB = 0;

    float* oA = out + ((size_t)(btile + bA) * OUT + (otile + o)) * 8;
    float* oB = out + ((size_t)(btile + bB) * OUT + (otile + o)) * 8;
    float4 v0, v1;
    v0.x = (float)((rawA >> 7) & 1); v0.y = (float)((rawA >> 6) & 1);
    v0.z = (float)((rawA >> 5) & 1); v0.w = (float)((rawA >> 4) & 1);
    v1.x = (float)((rawA >> 3) & 1); v1.y = (float)((rawA >> 2) & 1);
    v1.z = (float)((rawA >> 1) & 1); v1.w = (float)( rawA       & 1);
    ((float4*)oA)[0] = v0; ((float4*)oA)[1] = v1;
    v0.x = (float)((rawB >> 7) & 1); v0.y = (float)((rawB >> 6) & 1);
    v0.z = (float)((rawB >> 5) & 1); v0.w = (float)((rawB >> 4) & 1);
    v1.x = (float)((rawB >> 3) & 1); v1.y = (float)((rawB >> 2) & 1);
    v1.z = (float)((rawB >> 1) & 1); v1.w = (float)( rawB       & 1);
    ((float4*)oB)[0] = v0; ((float4*)oB)[1] = v1;
}

// ---------------- launch ----------------
extern "C" void kernel_launch(void* const* d_in, const int* in_sizes, int n_in,
                              void* d_out, int out_size) {
    const float* x = (const float*)d_in[0];
    const float* w = (const float*)d_in[1];
    if (n_in >= 2 && in_sizes[0] > in_sizes[1]) {   // x (1M) is smaller than w (4M)
        const float* tmp = x; x = w; w = tmp;
    }
    const int NT = BB * INN + OUT * INN;
    encode_kernel<<<(NT + 255) / 256, 256>>>(x, w);
    lut_kernel<<<256, 256>>>();
    cudaFuncSetAttribute(main_kernel, cudaFuncAttributeMaxDynamicSharedMemorySize, SM_TOTAL);
    main_kernel<<<128, 1024, SM_TOTAL>>>((float*)d_out);
}

// round 5
// speedup vs baseline: 3.3075x; 3.3075x over previous
#include <cuda_runtime.h>
#include <stdint.h>

#define BB  256
#define INN 512
#define OUT 1024

// ---------------- global scratch (no allocations allowed) ----------------
__device__ __align__(16) uint8_t g_xb[BB * INN];    // raw fp8 bytes of x
__device__ __align__(16) uint8_t g_wb[OUT * INN];   // raw fp8 bytes of w

// ---------------- kernel 1: spike bits -> fp8 bytes (2 bytes / thread) -----
__global__ void encode_kernel(const float* __restrict__ x, const float* __restrict__ w) {
    int tid = blockIdx.x * blockDim.x + threadIdx.x;
    const int NX2 = BB * INN / 2;            // 65536 two-byte units in x
    const int NT2 = NX2 + OUT * INN / 2;     // + 262144 in w
    if (tid >= NT2) return;
    bool isx = tid < NX2;
    const uint4* src = isx ? ((const uint4*)x) + (size_t)tid * 4
                           : ((const uint4*)w) + (size_t)(tid - NX2) * 4;
    uint4 a = src[0], b = src[1], c = src[2], d = src[3];
    unsigned b0 = (a.x ? 128u : 0u) | (a.y ? 64u : 0u) | (a.z ? 32u : 0u) | (a.w ? 16u : 0u)
                | (b.x ?   8u : 0u) | (b.y ?  4u : 0u) | (b.z ?  2u : 0u) | (b.w ?  1u : 0u);
    unsigned b1 = (c.x ? 128u : 0u) | (c.y ? 64u : 0u) | (c.z ? 32u : 0u) | (c.w ? 16u : 0u)
                | (d.x ?   8u : 0u) | (d.y ?  4u : 0u) | (d.z ?  2u : 0u) | (d.w ?  1u : 0u);
    unsigned short v = (unsigned short)(b0 | (b1 << 8));
    if (isx) *(unsigned short*)(g_xb + (size_t)tid * 2) = v;
    else     *(unsigned short*)(g_wb + (size_t)(tid - NX2) * 2) = v;
}

// ---------------- kernel 2: hardware-FP8 sequential chain ----------------
#define OT 128
#define BT 16
#define WROW 257                         // u32 stride per w row (odd -> conflict-free)
#define SMW_OFF 16384                    // x pairs occupy [0, 16384)
#define SM_TOTAL (16384 + 128 * WROW * 4)   // 147968 bytes

// one fp8-exact step on a packed pair of chains:
//   p  = quant_e4m3(x*w)   (f16 mul exact, satfinite == clamp-to-448)
//   acc= quant_e4m3(acc+p) (f16 add + RNE-to-fp8: innocuous double rounding, 11 >= 2*4+2)
#define STEP(X2, W2)                                                                   \
    {                                                                                  \
        unsigned pr, p2, s;                                                            \
        unsigned short p8;                                                             \
        asm("mul.rn.f16x2 %0, %1, %2;" : "=r"(pr) : "r"(X2), "r"(W2));                 \
        asm("cvt.rn.satfinite.e4m3x2.f16x2 %0, %1;" : "=h"(p8) : "r"(pr));             \
        asm("cvt.rn.f16x2.e4m3x2 %0, %1;" : "=r"(p2) : "h"(p8));                       \
        asm("add.rn.f16x2 %0, %1, %2;" : "=r"(s) : "r"(acc2), "r"(p2));                \
        asm("cvt.rn.satfinite.e4m3x2.f16x2 %0, %1;" : "=h"(a8) : "r"(s));              \
        asm("cvt.rn.f16x2.e4m3x2 %0, %1;" : "=r"(acc2) : "h"(a8));                     \
    }

__global__ __launch_bounds__(1024, 1)
void main_kernel(float* __restrict__ out) {
    extern __shared__ uint8_t sm[];
    unsigned* smx = (unsigned*)sm;              // 8 pair-rows x 512 f16x2 (xA,xB)
    unsigned* smw = (unsigned*)(sm + SMW_OFF);  // 128 rows x 256 f16x2 (w pairs), stride 257
    int t = threadIdx.x;
    int otile = (blockIdx.x & 7) * OT;
    int btile = (blockIdx.x >> 3) * BT;

    // ---- preload w tile as f16 (one-time cvt) ----
    #pragma unroll
    for (int k = 0; k < 16; k++) {
        int idx = t + k * 1024;                 // 0..16383 u32 chunks of w bytes
        int row = idx >> 7, c4 = idx & 127;
        unsigned wb4 = *(const unsigned*)(g_wb + (size_t)(otile + row) * INN + c4 * 4);
        unsigned h01, h23;
        asm("cvt.rn.f16x2.e4m3x2 %0, %1;" : "=r"(h01) : "h"((unsigned short)(wb4 & 0xffffu)));
        asm("cvt.rn.f16x2.e4m3x2 %0, %1;" : "=r"(h23) : "h"((unsigned short)(wb4 >> 16)));
        smw[row * WROW + c4 * 2]     = h01;     // halves (w_{4c4},   w_{4c4+1})
        smw[row * WROW + c4 * 2 + 1] = h23;     // halves (w_{4c4+2}, w_{4c4+3})
    }
    // ---- preload x chain-pairs as f16x2: lane0 = batch bA, lane1 = bA+8 ----
    {
        int pair = t >> 7, c4 = t & 127;
        unsigned xA4 = *(const unsigned*)(g_xb + (size_t)(btile + pair) * INN + c4 * 4);
        unsigned xB4 = *(const unsigned*)(g_xb + (size_t)(btile + pair + 8) * INN + c4 * 4);
        #pragma unroll
        for (int j = 0; j < 4; j++) {
            unsigned xpk, xh;
            asm("prmt.b32 %0, %1, %2, %3;" : "=r"(xpk)
                : "r"(xA4), "r"(xB4), "r"(0x40 + 0x11 * j));   // (xA_j, xB_j)
            asm("cvt.rn.f16x2.e4m3x2 %0, %1;" : "=r"(xh) : "h"((unsigned short)xpk));
            smx[pair * 512 + c4 * 4 + j] = xh;
        }
    }
    __syncthreads();

    int o = t & 127, bA = t >> 7;
    const unsigned* ws = smw + o * WROW;        // per-lane, conflict-free (stride 257)
    const uint2*    xp = (const uint2*)(smx + bA * 512);  // warp-uniform -> broadcast LDS.64

    unsigned acc2 = 0;                          // f16x2 (+0, +0)
    unsigned short a8 = 0;

    #pragma unroll 8
    for (int i2 = 0; i2 < 256; i2++) {
        unsigned wh  = ws[i2];                  // halves (w_{2i}, w_{2i+1})
        uint2    xv  = xp[i2];                  // (x2e, x2o) in one LDS.64
        unsigned w2;
        asm("prmt.b32 %0, %1, %1, %2;" : "=r"(w2) : "r"(wh), "r"(0x1010));  // (w_e, w_e)
        STEP(xv.x, w2);
        asm("prmt.b32 %0, %1, %1, %2;" : "=r"(w2) : "r"(wh), "r"(0x3232));  // (w_o, w_o)
        STEP(xv.y, w2);
    }

    int rawA = a8 & 0xff;        if ((rawA & 0x7f) == 0) rawA = 0;  // fold any +/-0
    int rawB = (a8 >> 8) & 0xff; if ((rawB & 0x7f) == 0) rawB = 0;

    float* oA = out + ((size_t)(btile + bA) * OUT + (otile + o)) * 8;
    float* oB = out + ((size_t)(btile + bA + 8) * OUT + (otile + o)) * 8;
    float4 v0, v1;
    v0.x = (float)((rawA >> 7) & 1); v0.y = (float)((rawA >> 6) & 1);
    v0.z = (float)((rawA >> 5) & 1); v0.w = (float)((rawA >> 4) & 1);
    v1.x = (float)((rawA >> 3) & 1); v1.y = (float)((rawA >> 2) & 1);
    v1.z = (float)((rawA >> 1) & 1); v1.w = (float)( rawA       & 1);
    ((float4*)oA)[0] = v0; ((float4*)oA)[1] = v1;
    v0.x = (float)((rawB >> 7) & 1); v0.y = (float)((rawB >> 6) & 1);
    v0.z = (float)((rawB >> 5) & 1); v0.w = (float)((rawB >> 4) & 1);
    v1.x = (float)((rawB >> 3) & 1); v1.y = (float)((rawB >> 2) & 1);
    v1.z = (float)((rawB >> 1) & 1); v1.w = (float)( rawB       & 1);
    ((float4*)oB)[0] = v0; ((float4*)oB)[1] = v1;
}

// ---------------- launch ----------------
extern "C" void kernel_launch(void* const* d_in, const int* in_sizes, int n_in,
                              void* d_out, int out_size) {
    const float* x = (const float*)d_in[0];
    const float* w = (const float*)d_in[1];
    if (n_in >= 2 && in_sizes[0] > in_sizes[1]) {   // x (1M floats) < w (4M floats)
        const float* tmp = x; x = w; w = tmp;
    }
    const int NT2 = BB * INN / 2 + OUT * INN / 2;   // 327680 two-byte units
    encode_kernel<<<(NT2 + 255) / 256, 256>>>(x, w);
    cudaFuncSetAttribute(main_kernel, cudaFuncAttributeMaxDynamicSharedMemorySize, SM_TOTAL);
    main_kernel<<<128, 1024, SM_TOTAL>>>((float*)d_out);
}

// round 6
// speedup vs baseline: 3.5518x; 1.0738x over previous
#include <cuda_runtime.h>
#include <stdint.h>

#define BB  256
#define INN 512
#define OUT 1024

// ---------------- global scratch (no allocations allowed) ----------------
__device__ __align__(16) uint8_t g_xb[BB * INN];    // raw fp8 bytes of x
__device__ __align__(16) uint8_t g_wb[OUT * INN];   // raw fp8 bytes of w

// ---------------- kernel 1: spike bits -> fp8 bytes (4 bytes / thread) -----
__global__ void encode_kernel(const float* __restrict__ x, const float* __restrict__ w) {
    int tid = blockIdx.x * blockDim.x + threadIdx.x;   // one u32 (4 fp8 bytes)
    const int NX4 = BB * INN / 4;                      // 32768 u32 units in x
    bool isx = tid < NX4;
    const uint4* src = isx ? ((const uint4*)x) + (size_t)tid * 8
                           : ((const uint4*)w) + (size_t)(tid - NX4) * 8;
    uint4 v0 = src[0], v1 = src[1], v2 = src[2], v3 = src[3];
    uint4 v4 = src[4], v5 = src[5], v6 = src[6], v7 = src[7];
    unsigned word = 0;
    #pragma unroll
    for (int b = 0; b < 4; b++) {
        uint4 a = (b == 0) ? v0 : (b == 1) ? v2 : (b == 2) ? v4 : v6;
        uint4 c = (b == 0) ? v1 : (b == 1) ? v3 : (b == 2) ? v5 : v7;
        unsigned byte = (a.x ? 128u : 0u) | (a.y ? 64u : 0u) | (a.z ? 32u : 0u) | (a.w ? 16u : 0u)
                      | (c.x ?   8u : 0u) | (c.y ?  4u : 0u) | (c.z ?  2u : 0u) | (c.w ?  1u : 0u);
        word |= byte << (8 * b);
    }
    if (isx) ((unsigned*)g_xb)[tid] = word;
    else     ((unsigned*)g_wb)[tid - NX4] = word;
}

// ---------------- kernel 2: hardware-FP8 sequential chain ----------------
#define OT 64
#define BT 32
#define WROW 516                          // u32 stride per dup-w row (129 uint4: odd -> conflict-free)
#define SMW_OFF 32768                     // x pairs occupy [0, 32768)
#define SM_TOTAL (SMW_OFF + OT * WROW * 4)   // 32768 + 132096 = 164864 bytes

// one fp8-exact step on a packed pair of chains:
//   p  = quant_e4m3(x*w)   (f16 mul exact, satfinite == clamp-to-448)
//   acc= quant_e4m3(acc+p) (f16 add + RNE-to-fp8: innocuous double rounding, 11 >= 2*4+2)
#define STEP(X2, W2)                                                                   \
    {                                                                                  \
        unsigned pr, p2, s;                                                            \
        unsigned short p8;                                                             \
        asm("mul.rn.f16x2 %0, %1, %2;" : "=r"(pr) : "r"(X2), "r"(W2));                 \
        asm("cvt.rn.satfinite.e4m3x2.f16x2 %0, %1;" : "=h"(p8) : "r"(pr));             \
        asm("cvt.rn.f16x2.e4m3x2 %0, %1;" : "=r"(p2) : "h"(p8));                       \
        asm("add.rn.f16x2 %0, %1, %2;" : "=r"(s) : "r"(acc2), "r"(p2));                \
        asm("cvt.rn.satfinite.e4m3x2.f16x2 %0, %1;" : "=h"(a8) : "r"(s));              \
        asm("cvt.rn.f16x2.e4m3x2 %0, %1;" : "=r"(acc2) : "h"(a8));                     \
    }

__global__ __launch_bounds__(1024, 1)
void main_kernel(float* __restrict__ out) {
    extern __shared__ uint8_t sm[];
    unsigned* smx = (unsigned*)sm;              // 16 pair-rows x 512 f16x2 (xA,xB)
    unsigned* smw = (unsigned*)(sm + SMW_OFF);  // 64 rows x 512 DUPLICATED f16x2, stride 516
    int t = threadIdx.x;
    int otile = (blockIdx.x & 15) * OT;
    int btile = (blockIdx.x >> 4) * BT;

    // ---- preload w tile as duplicated f16x2 (one-time cvt + prmt) ----
    #pragma unroll
    for (int k = 0; k < 8; k++) {
        int idx = t + k * 1024;                 // 0..8191 u32 chunks of w bytes
        int row = idx >> 7, c4 = idx & 127;
        unsigned wb4 = *(const unsigned*)(g_wb + (size_t)(otile + row) * INN + c4 * 4);
        unsigned h01, h23, d0, d1, d2, d3;
        asm("cvt.rn.f16x2.e4m3x2 %0, %1;" : "=r"(h01) : "h"((unsigned short)(wb4 & 0xffffu)));
        asm("cvt.rn.f16x2.e4m3x2 %0, %1;" : "=r"(h23) : "h"((unsigned short)(wb4 >> 16)));
        asm("prmt.b32 %0, %1, %1, %2;" : "=r"(d0) : "r"(h01), "r"(0x1010));  // (w0,w0)
        asm("prmt.b32 %0, %1, %1, %2;" : "=r"(d1) : "r"(h01), "r"(0x3232));  // (w1,w1)
        asm("prmt.b32 %0, %1, %1, %2;" : "=r"(d2) : "r"(h23), "r"(0x1010));  // (w2,w2)
        asm("prmt.b32 %0, %1, %1, %2;" : "=r"(d3) : "r"(h23), "r"(0x3232));  // (w3,w3)
        unsigned* dst = smw + row * WROW + c4 * 4;
        dst[0] = d0; dst[1] = d1; dst[2] = d2; dst[3] = d3;
    }
    // ---- preload x chain-pairs as f16x2: halves = batches (bp, bp+16) ----
    #pragma unroll
    for (int k = 0; k < 2; k++) {
        int idx = t + k * 1024;                 // 0..2047
        int pair = idx >> 7, c4 = idx & 127;
        unsigned xA4 = *(const unsigned*)(g_xb + (size_t)(btile + pair) * INN + c4 * 4);
        unsigned xB4 = *(const unsigned*)(g_xb + (size_t)(btile + pair + 16) * INN + c4 * 4);
        #pragma unroll
        for (int j = 0; j < 4; j++) {
            unsigned xpk, xh;
            asm("prmt.b32 %0, %1, %2, %3;" : "=r"(xpk)
                : "r"(xA4), "r"(xB4), "r"(0x40 + 0x11 * j));   // (xA_j, xB_j)
            asm("cvt.rn.f16x2.e4m3x2 %0, %1;" : "=r"(xh) : "h"((unsigned short)xpk));
            smx[pair * 512 + c4 * 4 + j] = xh;
        }
    }
    __syncthreads();

    int o = t & 63, pair = t >> 6;
    const uint4* wsv = (const uint4*)(smw + o * WROW);      // per-lane, conflict-free
    const uint4* xpv = (const uint4*)(smx + pair * 512);    // warp-uniform -> broadcast

    unsigned acc2 = 0;                          // f16x2 (+0, +0)
    unsigned short a8 = 0;

    #pragma unroll 8
    for (int j = 0; j < 128; j++) {
        uint4 wv = wsv[j];                      // dup-w for steps 4j..4j+3
        uint4 xv = xpv[j];                      // x pairs for steps 4j..4j+3
        STEP(xv.x, wv.x);
        STEP(xv.y, wv.y);
        STEP(xv.z, wv.z);
        STEP(xv.w, wv.w);
    }

    int rawA = a8 & 0xff;        if ((rawA & 0x7f) == 0) rawA = 0;  // fold any +/-0
    int rawB = (a8 >> 8) & 0xff; if ((rawB & 0x7f) == 0) rawB = 0;

    float* oA = out + ((size_t)(btile + pair) * OUT + (otile + o)) * 8;
    float* oB = out + ((size_t)(btile + pair + 16) * OUT + (otile + o)) * 8;
    float4 v0, v1;
    v0.x = (float)((rawA >> 7) & 1); v0.y = (float)((rawA >> 6) & 1);
    v0.z = (float)((rawA >> 5) & 1); v0.w = (float)((rawA >> 4) & 1);
    v1.x = (float)((rawA >> 3) & 1); v1.y = (float)((rawA >> 2) & 1);
    v1.z = (float)((rawA >> 1) & 1); v1.w = (float)( rawA       & 1);
    ((float4*)oA)[0] = v0; ((float4*)oA)[1] = v1;
    v0.x = (float)((rawB >> 7) & 1); v0.y = (float)((rawB >> 6) & 1);
    v0.z = (float)((rawB >> 5) & 1); v0.w = (float)((rawB >> 4) & 1);
    v1.x = (float)((rawB >> 3) & 1); v1.y = (float)((rawB >> 2) & 1);
    v1.z = (float)((rawB >> 1) & 1); v1.w = (float)( rawB       & 1);
    ((float4*)oB)[0] = v0; ((float4*)oB)[1] = v1;
}

// ---------------- launch ----------------
extern "C" void kernel_launch(void* const* d_in, const int* in_sizes, int n_in,
                              void* d_out, int out_size) {
    const float* x = (const float*)d_in[0];
    const float* w = (const float*)d_in[1];
    if (n_in >= 2 && in_sizes[0] > in_sizes[1]) {   // x (1M floats) < w (4M floats)
        const float* tmp = x; x = w; w = tmp;
    }
    const int NT4 = (BB * INN + OUT * INN) / 4;     // 163840 u32 units
    encode_kernel<<<NT4 / 256, 256>>>(x, w);
    cudaFuncSetAttribute(main_kernel, cudaFuncAttributeMaxDynamicSharedMemorySize, SM_TOTAL);
    main_kernel<<<128, 1024, SM_TOTAL>>>((float*)d_out);
}